// round 16
// baseline (speedup 1.0000x reference)
#include <cuda_runtime.h>
#include <cuda_fp16.h>

#define NN      30000
#define NPAD    30080
#define KNBR    20
#define DD      128
#define K1      384
#define K2      256
#define N_TILES 235
#define PREP_BLKS 321
#define AGG_BLKS  3750

typedef unsigned long long u64;
typedef unsigned int u32;

// ---------------- global scratch (zero-init; rows >= NN stay zero) ----------------
__device__ __half g_Ah[(size_t)NPAD * K1];
__device__ __half g_W1h[DD * K1];   // [n][k] transposed W1 (fp16)
__device__ __half g_W2h[DD * K2];   // [n][k] transposed W2[0:256] (fp16)
__device__ float g_cv[DD];
__device__ int   g_cnt[N_TILES + 1];   // [0..234]=tile arrivals, [235]=prep arrivals

// ---------------- helpers ----------------
__device__ __forceinline__ u32 smem_u32(const void* p) {
    u32 a;
    asm("{ .reg .u64 t; cvta.to.shared.u64 t, %1; cvt.u32.u64 %0, t; }" : "=r"(a) : "l"(p));
    return a;
}
#define SWZ(o) ((o) ^ (((o) >> 3) & 0x70))

__device__ __forceinline__ u64 fma2(u64 a, u64 b, u64 c) {
    u64 d;
    asm("fma.rn.f32x2 %0, %1, %2, %3;" : "=l"(d) : "l"(a), "l"(b), "l"(c));
    return d;
}
__device__ __forceinline__ u64 add2(u64 a, u64 b) {
    u64 d;
    asm("add.rn.f32x2 %0, %1, %2;" : "=l"(d) : "l"(a), "l"(b));
    return d;
}
__device__ __forceinline__ u64 pack2(float x) {
    u64 d;
    unsigned r = __float_as_uint(x);
    asm("mov.b64 %0, {%1, %2};" : "=l"(d) : "r"(r), "r"(r));
    return d;
}
__device__ __forceinline__ void unpack2(u64 v, float& lo, float& hi) {
    unsigned a, b;
    asm("mov.b64 {%0, %1}, %2;" : "=r"(a), "=r"(b) : "l"(v));
    lo = __uint_as_float(a);
    hi = __uint_as_float(b);
}
__device__ __forceinline__ void unpack2i(u64 v, unsigned& lo, unsigned& hi) {
    asm("mov.b64 {%0, %1}, %2;" : "=r"(lo), "=r"(hi) : "l"(v));
}
__device__ __forceinline__ u64 pack4(unsigned short a, unsigned short b,
                                     unsigned short c, unsigned short d) {
    return (u64)a | ((u64)b << 16) | ((u64)c << 32) | ((u64)d << 48);
}
__device__ __forceinline__ u64 hi4(float4 v) {
    return pack4(__half_as_ushort(__float2half_rn(v.x)),
                 __half_as_ushort(__float2half_rn(v.y)),
                 __half_as_ushort(__float2half_rn(v.z)),
                 __half_as_ushort(__float2half_rn(v.w)));
}

// Packed 2-lane cos, x in [0,~1.2e4]: Cody-Waite mod-pi (q<2^12 -> q*P1 exact),
// MUFU.COS on |r|<=pi/2, sign flip by parity of q.
__device__ __forceinline__ u64 cos2(u64 x2, u64 INVPI2, u64 MAGIC2, u64 NMAGIC2,
                                    u64 P1N2, u64 P2N2, u64 P3N2) {
    u64 qm2 = fma2(x2, INVPI2, MAGIC2);
    unsigned iq0, iq1;
    unpack2i(qm2, iq0, iq1);
    u64 q2 = add2(qm2, NMAGIC2);
    u64 r2 = fma2(q2, P1N2, x2);
    r2 = fma2(q2, P2N2, r2);
    r2 = fma2(q2, P3N2, r2);
    float rl, rh;
    unpack2(r2, rl, rh);
    unsigned ul = __float_as_uint(__cosf(rl)) ^ (iq0 << 31);
    unsigned uh = __float_as_uint(__cosf(rh)) ^ (iq1 << 31);
    u64 d;
    asm("mov.b64 %0, {%1, %2};" : "=l"(d) : "r"(ul), "r"(uh));
    return d;
}
__device__ __forceinline__ float fast_cos(float x) {
    const float MAGIC = 12582912.0f;
    float qm = fmaf(x, 0.31830988618379067f, MAGIC);
    int iq = __float_as_int(qm);
    float q = qm - MAGIC;
    float r = fmaf(q, -3.140625f, x);
    r = fmaf(q, -9.67502593994140625e-4f, r);
    r = fmaf(q, -1.5099579909783764e-7f, r);
    float c = __cosf(r);
    return __int_as_float(__float_as_int(c) ^ (iq << 31));
}

__device__ __forceinline__ void ldsm4(u32 (&r)[4], u32 addr) {
    asm volatile("ldmatrix.sync.aligned.m8n8.x4.shared.b16 {%0,%1,%2,%3}, [%4];"
                 : "=r"(r[0]), "=r"(r[1]), "=r"(r[2]), "=r"(r[3]) : "r"(addr));
}
__device__ __forceinline__ void mma16816(float (&c)[4], const u32 (&a)[4], u32 b0, u32 b1) {
    asm volatile(
        "mma.sync.aligned.m16n8k16.row.col.f32.f16.f16.f32 "
        "{%0,%1,%2,%3}, {%4,%5,%6,%7}, {%8,%9}, {%0,%1,%2,%3};"
        : "+f"(c[0]), "+f"(c[1]), "+f"(c[2]), "+f"(c[3])
        : "r"(a[0]), "r"(a[1]), "r"(a[2]), "r"(a[3]), "r"(b0), "r"(b1));
}
__device__ __forceinline__ void cp16(u32 dst, const void* src) {
    asm volatile("cp.async.cg.shared.global [%0], [%1], 16;" :: "r"(dst), "l"(src));
}
#define CP_COMMIT() asm volatile("cp.async.commit_group;" ::: "memory")
#define CP_WAIT(N)  asm volatile("cp.async.wait_group %0;" :: "n"(N) : "memory")

// ============================ agg + prep (merged grid, 4 CTAs/SM) ============================
// blocks [0,321): prep (W transpose + cvec); [321, 4071): gather (8 nodes/block)
__global__ void __launch_bounds__(256, 4)
agg_kernel(const float* __restrict__ nf, const float* __restrict__ ts,
           const float* __restrict__ ef, const int* __restrict__ nbrs,
           const int* __restrict__ eidx, const float* __restrict__ etim,
           const float* __restrict__ tw, const float* __restrict__ tb,
           const float* __restrict__ W1, const float* __restrict__ W2,
           const float* __restrict__ b2) {
    const int blk = blockIdx.x;
    if (blk < PREP_BLKS) {
        const int pb = blk;
        if (pb < 192) {                           // W1: [384][128] -> [n][384]
            int idx = pb * 256 + threadIdx.x;
            int k = idx >> 7, n = idx & 127;
            g_W1h[n * K1 + k] = __float2half_rn(W1[k * DD + n]);
        } else if (pb < 320) {                    // W2 rows 0..255 -> [n][256]
            int i2 = (pb - 192) * 256 + threadIdx.x;
            int k = i2 >> 7, n = i2 & 127;
            g_W2h[n * K2 + k] = __float2half_rn(W2[k * DD + n]);
        } else {                                  // cvec
            __shared__ float cb[DD];
            int c = threadIdx.x;
            if (c < DD) cb[c] = fast_cos(fabsf(tb[c]));
            __syncthreads();
            if (c < DD) {
                float a = b2[c];
                for (int d = 0; d < DD; ++d)
                    a = fmaf(cb[d], W2[(size_t)(2 * DD + d) * DD + c], a);
                g_cv[c] = a;
            }
        }
        __threadfence();
        __syncthreads();
        if (threadIdx.x == 0) atomicAdd(&g_cnt[N_TILES], 1);
        return;
    }

    const int ab = blk - PREP_BLKS;               // 0..3749
    const int lane = threadIdx.x & 31, wid = threadIdx.x >> 5;
    const int n = ab * 8 + wid;                   // 3750 * 8 = 30000 exactly

    const ulonglong2 tw2 = *(const ulonglong2*)(tw + lane * 4);
    const ulonglong2 tb2 = *(const ulonglong2*)(tb + lane * 4);
    const u64 INVPI2  = pack2(0.31830988618379067f);
    const u64 MAGIC2  = pack2(12582912.0f);
    const u64 NMAGIC2 = pack2(-12582912.0f);
    const u64 P1N2 = pack2(-3.140625f);
    const u64 P2N2 = pack2(-9.67502593994140625e-4f);
    const u64 P3N2 = pack2(-1.5099579909783764e-7f);

    int nbv = 0, eiv = 0; float etv = 0.f;
    if (lane < KNBR) {
        nbv = nbrs[n * KNBR + lane];
        eiv = eidx[n * KNBR + lane];
        etv = etim[n * KNBR + lane];
    }
    const float tsn = ts[n];

    u64 an0 = 0, an1 = 0, at0 = 0, at1 = 0, ae0 = 0, ae1 = 0;
#pragma unroll
    for (int k = 0; k < KNBR; ++k) {
        const int   nb = __shfl_sync(0xffffffffu, nbv, k);
        const int   ei = __shfl_sync(0xffffffffu, eiv, k);
        const float et = __shfl_sync(0xffffffffu, etv, k);
        const ulonglong2 f1 = *(const ulonglong2*)(nf + (size_t)nb * DD + lane * 4);
        const float4 f2f = __ldcs((const float4*)(ef + (size_t)ei * DD + lane * 4));
        const ulonglong2 f2 = *(const ulonglong2*)&f2f;
        an0 = add2(an0, f1.x); an1 = add2(an1, f1.y);
        ae0 = add2(ae0, f2.x); ae1 = add2(ae1, f2.y);
        const u64 dl2 = pack2(tsn - et);
        at0 = add2(at0, cos2(fma2(dl2, tw2.x, tb2.x),
                             INVPI2, MAGIC2, NMAGIC2, P1N2, P2N2, P3N2));
        at1 = add2(at1, cos2(fma2(dl2, tw2.y, tb2.y),
                             INVPI2, MAGIC2, NMAGIC2, P1N2, P2N2, P3N2));
    }

    float4 an, at, ae;
    unpack2(an0, an.x, an.y); unpack2(an1, an.z, an.w);
    unpack2(at0, at.x, at.y); unpack2(at1, at.z, at.w);
    unpack2(ae0, ae.x, ae.y); unpack2(ae1, ae.z, ae.w);
    size_t base = (size_t)n * K1 + lane * 4;
    *(u64*)(g_Ah + base)       = hi4(an);
    *(u64*)(g_Ah + base + 128) = hi4(at);
    *(u64*)(g_Ah + base + 256) = hi4(ae);

    __threadfence();                              // release g_Ah writes
    __syncthreads();
    if (threadIdx.x == 0) atomicAdd(&g_cnt[ab >> 4], 1);   // tile = node/128
}

// ============================ GEMM kernel (128-row tiles, double-buffered, PDL) ============================
// smem: SA x2 (32K) | SB x2 (32K) | SH (32K) | cv 512 | b1 512 = 99328 B -> 2 CTAs/SM
#define SA(b)  ((b) * 16384)
#define SBUF(b) (32768 + (b) * 16384)
#define SH     65536
#define SCV    98304
#define SB1    98816
#define SM_TOTAL 99328

__device__ __forceinline__ void stage_f16(u32 tile, const __half* __restrict__ src,
                                          int rowStride, int r0, int k0) {
    const int t = threadIdx.x;
#pragma unroll
    for (int i = 0; i < 4; ++i) {
        const int idx = t + i * 256;        // 1024 16B segments
        const int row = idx >> 3, seg = idx & 7;
        cp16(tile + SWZ(row * 128 + seg * 16),
             src + (size_t)(r0 + row) * rowStride + k0 + seg * 8);
    }
}
__device__ __forceinline__ void stage_nf(char* th, const float* __restrict__ nf,
                                         int n0, int k0) {
    const int t = threadIdx.x;
#pragma unroll
    for (int i = 0; i < 8; ++i) {
        const int idx = t + i * 256;        // 2048 float4
        const int row = idx >> 4, seg = idx & 15;
        const int n = n0 + row;
        float4 v = {0, 0, 0, 0};
        if (n < NN) v = *(const float4*)(nf + (size_t)n * DD + k0 + seg * 4);
        *(u64*)(th + SWZ(row * 128 + seg * 8)) = hi4(v);
    }
}

// one 64-deep K chunk; warp tile 32 rows x 64 cols
__device__ __forceinline__ void mma_chunk(u32 a_b, u32 b_b,
                                          int wm, int wn, int lane,
                                          float (&acc)[2][8][4]) {
    const int g = lane >> 3, r = lane & 7;
#pragma unroll
    for (int ks = 0; ks < 4; ++ks) {
        const int kb = ks * 32;
        u32 a[2][4], bh[4][4];
#pragma unroll
        for (int mi = 0; mi < 2; ++mi) {
            const int row = wm * 32 + mi * 16 + (g & 1) * 8 + r;
            ldsm4(a[mi], a_b + SWZ(row * 128 + kb + (g >> 1) * 16));
        }
#pragma unroll
        for (int gi = 0; gi < 4; ++gi) {
            const int nrow = wn * 64 + gi * 16 + (g >> 1) * 8 + r;
            ldsm4(bh[gi], b_b + SWZ(nrow * 128 + kb + (g & 1) * 16));
        }
#pragma unroll
        for (int mi = 0; mi < 2; ++mi)
#pragma unroll
            for (int nj = 0; nj < 8; ++nj) {
                const int gi = nj >> 1, p = (nj & 1) * 2;
                mma16816(acc[mi][nj], a[mi], bh[gi][p], bh[gi][p + 1]);
            }
    }
}

__global__ void __launch_bounds__(256)
gemm_kernel(const float* __restrict__ nf, const float* __restrict__ b1,
            float* __restrict__ out) {
    extern __shared__ char sm[];
    const u32 smb = smem_u32(sm);
    const int tid = threadIdx.x, lane = tid & 31, wid = tid >> 5;
    const int wm = wid & 3, wn = wid >> 2;        // 4x2 warp grid, 32x64 warp tile
    const int n0 = blockIdx.x * 128;

    // wait for prep + this tile's 16 (or 6) agg blocks
    if (tid == 0) {
        while (atomicAdd(&g_cnt[N_TILES], 0) < PREP_BLKS) __nanosleep(64);
        const int tgt = (blockIdx.x < N_TILES - 1) ? 16 : 6;
        while (atomicAdd(&g_cnt[blockIdx.x], 0) < tgt) __nanosleep(64);
        __threadfence();
    }
    __syncthreads();

    if (tid < DD) {
        ((float*)(sm + SCV))[tid] = g_cv[tid];
        ((float*)(sm + SB1))[tid] = b1[tid];
    }

    float acc[2][8][4];
#pragma unroll
    for (int a = 0; a < 2; ++a)
#pragma unroll
        for (int b = 0; b < 8; ++b)
#pragma unroll
            for (int q = 0; q < 4; ++q) acc[a][b][q] = 0.f;

    // ---------------- GEMM1: D = agg @ W1t^T (K=384, 6 chunks, pipelined) ----------------
    stage_f16(smb + SA(0), g_Ah, K1, n0, 0);
    stage_f16(smb + SBUF(0), g_W1h, K1, 0, 0);
    CP_COMMIT();
#pragma unroll 1
    for (int c = 0; c < 6; ++c) {
        const int cb = c & 1;
        if (c < 5) {
            stage_f16(smb + SA(cb ^ 1), g_Ah, K1, n0, (c + 1) * 64);
            stage_f16(smb + SBUF(cb ^ 1), g_W1h, K1, 0, (c + 1) * 64);
            CP_COMMIT();
            CP_WAIT(1);
        } else {
            CP_WAIT(0);
        }
        __syncthreads();
        mma_chunk(smb + SA(cb), smb + SBUF(cb), wm, wn, lane, acc);
        __syncthreads();
    }

    // ---------------- Epilogue 1: H = relu(D + 20*b1) -> SH (fp16) ----------------
    {
        const float* b1s = (const float*)(sm + SB1);
        char* th = sm + SH + wn * 16384;   // chunk index == wn
#pragma unroll
        for (int mi = 0; mi < 2; ++mi)
#pragma unroll
            for (int nj = 0; nj < 8; ++nj) {
                const int col = wn * 64 + nj * 8 + (lane & 3) * 2;
                const float bb0 = b1s[col], bb1 = b1s[col + 1];
                const int cbyte = (col & 63) * 2;
#pragma unroll
                for (int half = 0; half < 2; ++half) {
                    const int row = wm * 32 + mi * 16 + (lane >> 2) + half * 8;
                    float h0 = fmaxf(fmaf(20.f, bb0, acc[mi][nj][half * 2]),     0.f);
                    float h1 = fmaxf(fmaf(20.f, bb1, acc[mi][nj][half * 2 + 1]), 0.f);
                    u32 hp = (u32)__half_as_ushort(__float2half_rn(h0)) |
                             ((u32)__half_as_ushort(__float2half_rn(h1)) << 16);
                    *(u32*)(th + SWZ(row * 128 + cbyte)) = hp;
                }
            }
    }

    // ---------------- GEMM2: D = [H | nf] @ W2t^T + cvec (K=256, 4 chunks) ----------------
    {
        const float* cvs = (const float*)(sm + SCV);
#pragma unroll
        for (int mi = 0; mi < 2; ++mi)
#pragma unroll
            for (int nj = 0; nj < 8; ++nj) {
                const int col = wn * 64 + nj * 8 + (lane & 3) * 2;
                acc[mi][nj][0] = cvs[col];
                acc[mi][nj][1] = cvs[col + 1];
                acc[mi][nj][2] = cvs[col];
                acc[mi][nj][3] = cvs[col + 1];
            }
    }
    stage_f16(smb + SBUF(0), g_W2h, K2, 0, 0);
    CP_COMMIT();
#pragma unroll 1
    for (int c = 0; c < 4; ++c) {
        const int cb = c & 1;
        if (c < 3) {
            stage_f16(smb + SBUF(cb ^ 1), g_W2h, K2, 0, (c + 1) * 64);
            CP_COMMIT();
        }
        if (c >= 2) stage_nf(sm + SA(cb), nf, n0, (c - 2) * 64);
        if (c < 3) CP_WAIT(1); else CP_WAIT(0);
        __syncthreads();
        const u32 a_b = (c < 2) ? (smb + SH + c * 16384) : (smb + SA(cb));
        mma_chunk(a_b, smb + SBUF(cb), wm, wn, lane, acc);
        __syncthreads();
    }

    // ---------------- Epilogue 2: out = D ----------------
#pragma unroll
    for (int mi = 0; mi < 2; ++mi)
#pragma unroll
        for (int nj = 0; nj < 8; ++nj) {
            const int col = wn * 64 + nj * 8 + (lane & 3) * 2;
#pragma unroll
            for (int half = 0; half < 2; ++half) {
                const int n = n0 + wm * 32 + mi * 16 + (lane >> 2) + half * 8;
                if (n < NN) {
                    float2 o = {acc[mi][nj][half * 2], acc[mi][nj][half * 2 + 1]};
                    *(float2*)(out + (size_t)n * DD + col) = o;
                }
            }
        }
}

extern "C" void kernel_launch(void* const* d_in, const int* in_sizes, int n_in,
                              void* d_out, int out_size) {
    const float* node_features = (const float*)d_in[0];
    const float* timestamps    = (const float*)d_in[1];
    const float* edge_features = (const float*)d_in[2];
    const int*   neighbors     = (const int*)d_in[3];
    const int*   edge_idxs     = (const int*)d_in[4];
    const float* edge_times    = (const float*)d_in[5];
    const float* time_w        = (const float*)d_in[6];
    const float* time_b        = (const float*)d_in[7];
    const float* W1            = (const float*)d_in[8];
    const float* b1            = (const float*)d_in[9];
    const float* W2            = (const float*)d_in[10];
    const float* b2            = (const float*)d_in[11];
    float* out = (float*)d_out;

    cudaFuncSetAttribute(gemm_kernel, cudaFuncAttributeMaxDynamicSharedMemorySize, SM_TOTAL);

    // reset arrival counters (captured as a memset node; no allocation)
    void* cntPtr = nullptr;
    cudaGetSymbolAddress(&cntPtr, g_cnt);
    cudaMemsetAsync(cntPtr, 0, sizeof(int) * (N_TILES + 1), 0);

    agg_kernel<<<PREP_BLKS + AGG_BLKS, 256>>>(
        node_features, timestamps, edge_features, neighbors, edge_idxs,
        edge_times, time_w, time_b, W1, W2, b2);

    // gemm: opt out of stream serialization (PDL); ordering enforced by g_cnt spins
    cudaLaunchAttribute attrs[1];
    attrs[0].id = cudaLaunchAttributeProgrammaticStreamSerialization;
    attrs[0].val.programmaticStreamSerializationAllowed = 1;
    cudaLaunchConfig_t cfg = {};
    cfg.gridDim = dim3(N_TILES, 1, 1);
    cfg.blockDim = dim3(256, 1, 1);
    cfg.dynamicSmemBytes = SM_TOTAL;
    cfg.stream = 0;
    cfg.attrs = attrs;
    cfg.numAttrs = 1;
    cudaLaunchKernelEx(&cfg, gemm_kernel, node_features, b1, out);
}

// round 17
// speedup vs baseline: 1.0911x; 1.0911x over previous
#include <cuda_runtime.h>
#include <cuda_fp16.h>

#define NN      30000
#define NPAD    30080
#define KNBR    20
#define DD      128
#define K1      384
#define K2      256
#define N_TILES 235
#define AGG_BLKS 3750
#define PREP_BLKS 2201   // 192 W1 + 128 W2 + 1 cvec + 1880 nf-convert

typedef unsigned long long u64;
typedef unsigned int u32;

// ---------------- global scratch (zero-init; rows >= NN stay zero) ----------------
__device__ __half g_Ah[(size_t)NPAD * K1];
__device__ __half g_NFh[(size_t)NPAD * DD];   // fp16 node_features
__device__ __half g_W1h[DD * K1];             // [n][k] transposed W1 (fp16)
__device__ __half g_W2h[DD * K2];             // [n][k] transposed W2[0:256] (fp16)
__device__ float g_cv[DD];

// ---------------- helpers ----------------
__device__ __forceinline__ u32 smem_u32(const void* p) {
    u32 a;
    asm("{ .reg .u64 t; cvta.to.shared.u64 t, %1; cvt.u32.u64 %0, t; }" : "=r"(a) : "l"(p));
    return a;
}
#define SWZ(o) ((o) ^ (((o) >> 3) & 0x70))

__device__ __forceinline__ u64 fma2(u64 a, u64 b, u64 c) {
    u64 d;
    asm("fma.rn.f32x2 %0, %1, %2, %3;" : "=l"(d) : "l"(a), "l"(b), "l"(c));
    return d;
}
__device__ __forceinline__ u64 add2(u64 a, u64 b) {
    u64 d;
    asm("add.rn.f32x2 %0, %1, %2;" : "=l"(d) : "l"(a), "l"(b));
    return d;
}
__device__ __forceinline__ u64 pack2(float x) {
    u64 d;
    unsigned r = __float_as_uint(x);
    asm("mov.b64 %0, {%1, %2};" : "=l"(d) : "r"(r), "r"(r));
    return d;
}
__device__ __forceinline__ void unpack2(u64 v, float& lo, float& hi) {
    unsigned a, b;
    asm("mov.b64 {%0, %1}, %2;" : "=r"(a), "=r"(b) : "l"(v));
    lo = __uint_as_float(a);
    hi = __uint_as_float(b);
}
__device__ __forceinline__ void unpack2i(u64 v, unsigned& lo, unsigned& hi) {
    asm("mov.b64 {%0, %1}, %2;" : "=r"(lo), "=r"(hi) : "l"(v));
}
__device__ __forceinline__ u64 pack4(unsigned short a, unsigned short b,
                                     unsigned short c, unsigned short d) {
    return (u64)a | ((u64)b << 16) | ((u64)c << 32) | ((u64)d << 48);
}
__device__ __forceinline__ u64 hi4(float4 v) {
    return pack4(__half_as_ushort(__float2half_rn(v.x)),
                 __half_as_ushort(__float2half_rn(v.y)),
                 __half_as_ushort(__float2half_rn(v.z)),
                 __half_as_ushort(__float2half_rn(v.w)));
}

// Packed 2-lane cos, x in [0,~1.2e4]: Cody-Waite mod-pi (q<2^12 -> q*P1 exact),
// MUFU.COS on |r|<=pi/2, sign flip by parity of q.
__device__ __forceinline__ u64 cos2(u64 x2, u64 INVPI2, u64 MAGIC2, u64 NMAGIC2,
                                    u64 P1N2, u64 P2N2, u64 P3N2) {
    u64 qm2 = fma2(x2, INVPI2, MAGIC2);
    unsigned iq0, iq1;
    unpack2i(qm2, iq0, iq1);
    u64 q2 = add2(qm2, NMAGIC2);
    u64 r2 = fma2(q2, P1N2, x2);
    r2 = fma2(q2, P2N2, r2);
    r2 = fma2(q2, P3N2, r2);
    float rl, rh;
    unpack2(r2, rl, rh);
    unsigned ul = __float_as_uint(__cosf(rl)) ^ (iq0 << 31);
    unsigned uh = __float_as_uint(__cosf(rh)) ^ (iq1 << 31);
    u64 d;
    asm("mov.b64 %0, {%1, %2};" : "=l"(d) : "r"(ul), "r"(uh));
    return d;
}
__device__ __forceinline__ float fast_cos(float x) {
    const float MAGIC = 12582912.0f;
    float qm = fmaf(x, 0.31830988618379067f, MAGIC);
    int iq = __float_as_int(qm);
    float q = qm - MAGIC;
    float r = fmaf(q, -3.140625f, x);
    r = fmaf(q, -9.67502593994140625e-4f, r);
    r = fmaf(q, -1.5099579909783764e-7f, r);
    float c = __cosf(r);
    return __int_as_float(__float_as_int(c) ^ (iq << 31));
}

__device__ __forceinline__ void ldsm4(u32 (&r)[4], u32 addr) {
    asm volatile("ldmatrix.sync.aligned.m8n8.x4.shared.b16 {%0,%1,%2,%3}, [%4];"
                 : "=r"(r[0]), "=r"(r[1]), "=r"(r[2]), "=r"(r[3]) : "r"(addr));
}
__device__ __forceinline__ void mma16816(float (&c)[4], const u32 (&a)[4], u32 b0, u32 b1) {
    asm volatile(
        "mma.sync.aligned.m16n8k16.row.col.f32.f16.f16.f32 "
        "{%0,%1,%2,%3}, {%4,%5,%6,%7}, {%8,%9}, {%0,%1,%2,%3};"
        : "+f"(c[0]), "+f"(c[1]), "+f"(c[2]), "+f"(c[3])
        : "r"(a[0]), "r"(a[1]), "r"(a[2]), "r"(a[3]), "r"(b0), "r"(b1));
}
__device__ __forceinline__ void cp16(u32 dst, const void* src) {
    asm volatile("cp.async.cg.shared.global [%0], [%1], 16;" :: "r"(dst), "l"(src));
}
#define CP_COMMIT() asm volatile("cp.async.commit_group;" ::: "memory")
#define CP_WAIT(N)  asm volatile("cp.async.wait_group %0;" :: "n"(N) : "memory")

// ============================ agg + prep (merged grid, 4 CTAs/SM) ============================
__global__ void __launch_bounds__(256, 4)
agg_kernel(const float* __restrict__ nf, const float* __restrict__ ts,
           const float* __restrict__ ef, const int* __restrict__ nbrs,
           const int* __restrict__ eidx, const float* __restrict__ etim,
           const float* __restrict__ tw, const float* __restrict__ tb,
           const float* __restrict__ W1, const float* __restrict__ W2,
           const float* __restrict__ b2) {
    const int blk = blockIdx.x;
    if (blk >= AGG_BLKS) {
        const int pb = blk - AGG_BLKS;
        if (pb < 192) {                           // W1: [384][128] -> [n][384]
            int idx = pb * 256 + threadIdx.x;
            int k = idx >> 7, n = idx & 127;
            g_W1h[n * K1 + k] = __float2half_rn(W1[k * DD + n]);
        } else if (pb < 320) {                    // W2 rows 0..255 -> [n][256]
            int i2 = (pb - 192) * 256 + threadIdx.x;
            int k = i2 >> 7, n = i2 & 127;
            g_W2h[n * K2 + k] = __float2half_rn(W2[k * DD + n]);
        } else if (pb == 320) {                   // cvec
            __shared__ float cb[DD];
            int c = threadIdx.x;
            if (c < DD) cb[c] = fast_cos(fabsf(tb[c]));
            __syncthreads();
            if (c < DD) {
                float a = b2[c];
                for (int d = 0; d < DD; ++d)
                    a = fmaf(cb[d], W2[(size_t)(2 * DD + d) * DD + c], a);
                g_cv[c] = a;
            }
        } else {                                  // nf -> fp16 (streaming convert)
            int idx = (pb - 321) * 256 + threadIdx.x;
            int e = idx * 8;
            if ((e >> 7) < NN) {
                float4 v0 = *(const float4*)(nf + e);
                float4 v1 = *(const float4*)(nf + e + 4);
                *(u64*)(g_NFh + e)     = hi4(v0);
                *(u64*)(g_NFh + e + 4) = hi4(v1);
            }
        }
        return;
    }

    const int lane = threadIdx.x & 31, wid = threadIdx.x >> 5;
    const int n = blk * 8 + wid;                  // 3750 * 8 = 30000 exactly

    const ulonglong2 tw2 = *(const ulonglong2*)(tw + lane * 4);
    const ulonglong2 tb2 = *(const ulonglong2*)(tb + lane * 4);
    const u64 INVPI2  = pack2(0.31830988618379067f);
    const u64 MAGIC2  = pack2(12582912.0f);
    const u64 NMAGIC2 = pack2(-12582912.0f);
    const u64 P1N2 = pack2(-3.140625f);
    const u64 P2N2 = pack2(-9.67502593994140625e-4f);
    const u64 P3N2 = pack2(-1.5099579909783764e-7f);

    int nbv = 0, eiv = 0; float etv = 0.f;
    if (lane < KNBR) {
        nbv = nbrs[n * KNBR + lane];
        eiv = eidx[n * KNBR + lane];
        etv = etim[n * KNBR + lane];
    }
    const float tsn = ts[n];

    u64 an0 = 0, an1 = 0, at0 = 0, at1 = 0, ae0 = 0, ae1 = 0;
#pragma unroll
    for (int k = 0; k < KNBR; ++k) {
        const int   nb = __shfl_sync(0xffffffffu, nbv, k);
        const int   ei = __shfl_sync(0xffffffffu, eiv, k);
        const float et = __shfl_sync(0xffffffffu, etv, k);
        const ulonglong2 f1 = *(const ulonglong2*)(nf + (size_t)nb * DD + lane * 4);
        const float4 f2f = __ldcs((const float4*)(ef + (size_t)ei * DD + lane * 4));
        const ulonglong2 f2 = *(const ulonglong2*)&f2f;
        an0 = add2(an0, f1.x); an1 = add2(an1, f1.y);
        ae0 = add2(ae0, f2.x); ae1 = add2(ae1, f2.y);
        const u64 dl2 = pack2(tsn - et);
        at0 = add2(at0, cos2(fma2(dl2, tw2.x, tb2.x),
                             INVPI2, MAGIC2, NMAGIC2, P1N2, P2N2, P3N2));
        at1 = add2(at1, cos2(fma2(dl2, tw2.y, tb2.y),
                             INVPI2, MAGIC2, NMAGIC2, P1N2, P2N2, P3N2));
    }

    float4 an, at, ae;
    unpack2(an0, an.x, an.y); unpack2(an1, an.z, an.w);
    unpack2(at0, at.x, at.y); unpack2(at1, at.z, at.w);
    unpack2(ae0, ae.x, ae.y); unpack2(ae1, ae.z, ae.w);
    size_t base = (size_t)n * K1 + lane * 4;
    *(u64*)(g_Ah + base)       = hi4(an);
    *(u64*)(g_Ah + base + 128) = hi4(at);
    *(u64*)(g_Ah + base + 256) = hi4(ae);
}

// ============================ GEMM kernel (128-row tiles, double-buffered) ============================
// smem: SA x2 (32K) | SB x2 (32K) | SH (32K) | cv 512 | b1 512 = 99328 B -> 2 CTAs/SM
#define SA(b)  ((b) * 16384)
#define SBUF(b) (32768 + (b) * 16384)
#define SH     65536
#define SCV    98304
#define SB1    98816
#define SM_TOTAL 99328

__device__ __forceinline__ void stage_f16(u32 tile, const __half* __restrict__ src,
                                          int rowStride, int r0, int k0) {
    const int t = threadIdx.x;
#pragma unroll
    for (int i = 0; i < 4; ++i) {
        const int idx = t + i * 256;        // 1024 16B segments
        const int row = idx >> 3, seg = idx & 7;
        cp16(tile + SWZ(row * 128 + seg * 16),
             src + (size_t)(r0 + row) * rowStride + k0 + seg * 8);
    }
}

// one 64-deep K chunk; warp tile 32 rows x 64 cols
__device__ __forceinline__ void mma_chunk(u32 a_b, u32 b_b,
                                          int wm, int wn, int lane,
                                          float (&acc)[2][8][4]) {
    const int g = lane >> 3, r = lane & 7;
#pragma unroll
    for (int ks = 0; ks < 4; ++ks) {
        const int kb = ks * 32;
        u32 a[2][4], bh[4][4];
#pragma unroll
        for (int mi = 0; mi < 2; ++mi) {
            const int row = wm * 32 + mi * 16 + (g & 1) * 8 + r;
            ldsm4(a[mi], a_b + SWZ(row * 128 + kb + (g >> 1) * 16));
        }
#pragma unroll
        for (int gi = 0; gi < 4; ++gi) {
            const int nrow = wn * 64 + gi * 16 + (g >> 1) * 8 + r;
            ldsm4(bh[gi], b_b + SWZ(nrow * 128 + kb + (g & 1) * 16));
        }
#pragma unroll
        for (int mi = 0; mi < 2; ++mi)
#pragma unroll
            for (int nj = 0; nj < 8; ++nj) {
                const int gi = nj >> 1, p = (nj & 1) * 2;
                mma16816(acc[mi][nj], a[mi], bh[gi][p], bh[gi][p + 1]);
            }
    }
}

__global__ void __launch_bounds__(256)
gemm_kernel(const float* __restrict__ b1, float* __restrict__ out) {
    extern __shared__ char sm[];
    const u32 smb = smem_u32(sm);
    const int tid = threadIdx.x, lane = tid & 31, wid = tid >> 5;
    const int wm = wid & 3, wn = wid >> 2;        // 4x2 warp grid, 32x64 warp tile
    const int n0 = blockIdx.x * 128;

    if (tid < DD) {
        ((float*)(sm + SCV))[tid] = g_cv[tid];
        ((float*)(sm + SB1))[tid] = b1[tid];
    }

    float acc[2][8][4];
#pragma unroll
    for (int a = 0; a < 2; ++a)
#pragma unroll
        for (int b = 0; b < 8; ++b)
#pragma unroll
            for (int q = 0; q < 4; ++q) acc[a][b][q] = 0.f;

    // ---------------- GEMM1: D = agg @ W1t^T (K=384, 6 chunks, pipelined) ----------------
    stage_f16(smb + SA(0), g_Ah, K1, n0, 0);
    stage_f16(smb + SBUF(0), g_W1h, K1, 0, 0);
    CP_COMMIT();
#pragma unroll 1
    for (int c = 0; c < 6; ++c) {
        const int cb = c & 1;
        if (c < 5) {
            stage_f16(smb + SA(cb ^ 1), g_Ah, K1, n0, (c + 1) * 64);
            stage_f16(smb + SBUF(cb ^ 1), g_W1h, K1, 0, (c + 1) * 64);
            CP_COMMIT();
            CP_WAIT(1);
        } else {
            CP_WAIT(0);
        }
        __syncthreads();
        mma_chunk(smb + SA(cb), smb + SBUF(cb), wm, wn, lane, acc);
        __syncthreads();
    }

    // Prefetch ALL of GEMM2's A-chunks (fp16 nf tiles into freed SA) + W2 chunk 0,
    // hidden behind epilogue 1.
    stage_f16(smb + SA(0), g_NFh, DD, n0, 0);
    stage_f16(smb + SA(1), g_NFh, DD, n0, 64);
    stage_f16(smb + SBUF(0), g_W2h, K2, 0, 0);
    CP_COMMIT();

    // ---------------- Epilogue 1: H = relu(D + 20*b1) -> SH (fp16) ----------------
    {
        const float* b1s = (const float*)(sm + SB1);
        char* th = sm + SH + wn * 16384;   // chunk index == wn
#pragma unroll
        for (int mi = 0; mi < 2; ++mi)
#pragma unroll
            for (int nj = 0; nj < 8; ++nj) {
                const int col = wn * 64 + nj * 8 + (lane & 3) * 2;
                const float bb0 = b1s[col], bb1 = b1s[col + 1];
                const int cbyte = (col & 63) * 2;
#pragma unroll
                for (int half = 0; half < 2; ++half) {
                    const int row = wm * 32 + mi * 16 + (lane >> 2) + half * 8;
                    float h0 = fmaxf(fmaf(20.f, bb0, acc[mi][nj][half * 2]),     0.f);
                    float h1 = fmaxf(fmaf(20.f, bb1, acc[mi][nj][half * 2 + 1]), 0.f);
                    u32 hp = (u32)__half_as_ushort(__float2half_rn(h0)) |
                             ((u32)__half_as_ushort(__float2half_rn(h1)) << 16);
                    *(u32*)(th + SWZ(row * 128 + cbyte)) = hp;
                }
            }
    }

    // ---------------- GEMM2: D = [H | nf] @ W2t^T + cvec (K=256, 4 chunks) ----------------
    {
        const float* cvs = (const float*)(sm + SCV);
#pragma unroll
        for (int mi = 0; mi < 2; ++mi)
#pragma unroll
            for (int nj = 0; nj < 8; ++nj) {
                const int col = wn * 64 + nj * 8 + (lane & 3) * 2;
                acc[mi][nj][0] = cvs[col];
                acc[mi][nj][1] = cvs[col + 1];
                acc[mi][nj][2] = cvs[col];
                acc[mi][nj][3] = cvs[col + 1];
            }
    }
#pragma unroll 1
    for (int c = 0; c < 4; ++c) {
        const int cb = c & 1;
        if (c < 3) {
            stage_f16(smb + SBUF(cb ^ 1), g_W2h, K2, 0, (c + 1) * 64);
            CP_COMMIT();
            CP_WAIT(1);
        } else {
            CP_WAIT(0);
        }
        __syncthreads();
        const u32 a_b = (c < 2) ? (smb + SH + c * 16384) : (smb + SA(c - 2));
        mma_chunk(a_b, smb + SBUF(cb), wm, wn, lane, acc);
        __syncthreads();
    }

    // ---------------- Epilogue 2: out = D ----------------
#pragma unroll
    for (int mi = 0; mi < 2; ++mi)
#pragma unroll
        for (int nj = 0; nj < 8; ++nj) {
            const int col = wn * 64 + nj * 8 + (lane & 3) * 2;
#pragma unroll
            for (int half = 0; half < 2; ++half) {
                const int n = n0 + wm * 32 + mi * 16 + (lane >> 2) + half * 8;
                if (n < NN) {
                    float2 o = {acc[mi][nj][half * 2], acc[mi][nj][half * 2 + 1]};
                    *(float2*)(out + (size_t)n * DD + col) = o;
                }
            }
        }
}

extern "C" void kernel_launch(void* const* d_in, const int* in_sizes, int n_in,
                              void* d_out, int out_size) {
    const float* node_features = (const float*)d_in[0];
    const float* timestamps    = (const float*)d_in[1];
    const float* edge_features = (const float*)d_in[2];
    const int*   neighbors     = (const int*)d_in[3];
    const int*   edge_idxs     = (const int*)d_in[4];
    const float* edge_times    = (const float*)d_in[5];
    const float* time_w        = (const float*)d_in[6];
    const float* time_b        = (const float*)d_in[7];
    const float* W1            = (const float*)d_in[8];
    const float* b1            = (const float*)d_in[9];
    const float* W2            = (const float*)d_in[10];
    const float* b2            = (const float*)d_in[11];
    float* out = (float*)d_out;

    cudaFuncSetAttribute(gemm_kernel, cudaFuncAttributeMaxDynamicSharedMemorySize, SM_TOTAL);

    agg_kernel<<<AGG_BLKS + PREP_BLKS, 256>>>(
        node_features, timestamps, edge_features, neighbors, edge_idxs,
        edge_times, time_w, time_b, W1, W2, b2);
    gemm_kernel<<<N_TILES, 256, SM_TOTAL>>>(b1, out);
}